// round 1
// baseline (speedup 1.0000x reference)
#include <cuda_runtime.h>
#include <cstdint>

// Problem constants (fixed shapes from setup_inputs)
#define NUM_P  16384
#define DIM    100
#define BATN   8192

#define TN      64     // n-tile per block
#define TP      128    // p-chunk per iteration
#define THREADS 256
#define PS      8      // P-axis splits
#define NTILES  (BATN / TN)                    // 128
#define CHUNKS_TOTAL (NUM_P / TP)              // 128
#define CHUNKS_PER_SPLIT (CHUNKS_TOTAL / PS)   // 16

// Scratch: packed (ordered_value << 32 | ~argmax_index) per sample
__device__ unsigned long long g_packed[BATN];

__device__ __forceinline__ unsigned f2ord(float f) {
    unsigned u = __float_as_uint(f);
    return (u & 0x80000000u) ? ~u : (u | 0x80000000u);
}
__device__ __forceinline__ float ord2f(unsigned u) {
    u = (u & 0x80000000u) ? (u & 0x7FFFFFFFu) : ~u;
    return __uint_as_float(u);
}
// Packed dual-FP32 FMA (sm_100+): d.lo += a.lo*b.lo ; d.hi += a.hi*b.hi
__device__ __forceinline__ void fma2(unsigned long long& d,
                                     unsigned long long a,
                                     unsigned long long b) {
    asm volatile("fma.rn.f32x2 %0, %1, %2, %0;" : "+l"(d) : "l"(a), "l"(b));
}

__global__ void k0_init(float* __restrict__ out_g) {
    int i = blockIdx.x * blockDim.x + threadIdx.x;
    if (i < NUM_P) out_g[i] = 0.0f;
    if (i < BATN)  g_packed[i] = 0ull;
}

extern __shared__ float smem_dyn[];

__global__ __launch_bounds__(THREADS, 2) void k1_main(
    const float* __restrict__ hP,
    const float* __restrict__ h,
    const float* __restrict__ volP)
{
    float* svol = smem_dyn;                      // TN * DIM
    float* shp  = smem_dyn + TN * DIM;           // TP * DIM
    float* sh_h = smem_dyn + TN * DIM + TP * DIM;// TP

    const int tid = threadIdx.x;
    const int nb  = blockIdx.x % NTILES;  // n-tile index
    const int pb  = blockIdx.x / NTILES;  // p-split index

    // Load this block's volP tile (contiguous region, coalesced float4 copy)
    {
        const float4* src = (const float4*)(volP + (size_t)nb * TN * DIM);
        float4* dst = (float4*)svol;
        #pragma unroll 4
        for (int i = tid; i < TN * DIM / 4; i += THREADS) dst[i] = src[i];
    }

    const int nt    = tid & 15;   // n lane: owns n = nt + 16*j (strided -> conflict-free LDS.128 phases)
    const int pbase = (tid >> 4) * 8;  // owns p = pbase .. pbase+7 within chunk

    float vmax[4];
    int   vidx[4];
    #pragma unroll
    for (int j = 0; j < 4; j++) { vmax[j] = -3.4e38f; vidx[j] = 0; }

    for (int c = 0; c < CHUNKS_PER_SPLIT; c++) {
        const int p0 = (pb * CHUNKS_PER_SPLIT + c) * TP;

        __syncthreads();  // protect shp (and initial svol) before overwrite
        {
            const float4* src = (const float4*)(hP + (size_t)p0 * DIM);
            float4* dst = (float4*)shp;
            #pragma unroll 4
            for (int i = tid; i < TP * DIM / 4; i += THREADS) dst[i] = src[i];
            if (tid < TP) sh_h[tid] = h[p0 + tid];
        }
        __syncthreads();

        unsigned long long acc[8][4];
        #pragma unroll
        for (int i = 0; i < 8; i++)
            #pragma unroll
            for (int j = 0; j < 4; j++) acc[i][j] = 0ull;

        #pragma unroll 5
        for (int d = 0; d < DIM; d += 4) {
            ulonglong2 b[4];
            #pragma unroll
            for (int j = 0; j < 4; j++)
                b[j] = *(const ulonglong2*)&svol[(nt + 16 * j) * DIM + d];
            #pragma unroll
            for (int i = 0; i < 8; i++) {
                ulonglong2 a = *(const ulonglong2*)&shp[(pbase + i) * DIM + d];
                #pragma unroll
                for (int j = 0; j < 4; j++) {
                    fma2(acc[i][j], a.x, b[j].x);
                    fma2(acc[i][j], a.y, b[j].y);
                }
            }
        }

        // Epilogue: fold d-pair, add h, merge running (max, argmax)
        #pragma unroll
        for (int i = 0; i < 8; i++) {
            const float hv = sh_h[pbase + i];
            const int   p  = p0 + pbase + i;
            #pragma unroll
            for (int j = 0; j < 4; j++) {
                float lo = __uint_as_float((unsigned)(acc[i][j]));
                float hi = __uint_as_float((unsigned)(acc[i][j] >> 32));
                float s  = lo + hi + hv;
                if (s > vmax[j]) { vmax[j] = s; vidx[j] = p; }  // '>' keeps earliest p
            }
        }
    }

    // Publish per-n winner: packed atomicMax (tie -> smaller index via ~idx)
    #pragma unroll
    for (int j = 0; j < 4; j++) {
        const int n = nb * TN + nt + 16 * j;
        unsigned long long pk = ((unsigned long long)f2ord(vmax[j]) << 32)
                              | (unsigned long long)(~(unsigned)vidx[j]);
        atomicMax(&g_packed[n], pk);
    }
}

__global__ void k2_final(float* __restrict__ out) {
    int n = blockIdx.x * blockDim.x + threadIdx.x;
    if (n >= BATN) return;
    unsigned long long pk = g_packed[n];
    unsigned ub = (unsigned)(pk >> 32);
    unsigned p  = ~(unsigned)pk;
    out[n]            = ord2f(ub);       // tot_ind_val
    out[BATN + n]     = (float)p;        // tot_ind (as float)
    atomicAdd(&out[2 * BATN + p], 1.0f / (float)BATN);  // g (exact pow2 summands)
}

extern "C" void kernel_launch(void* const* d_in, const int* in_sizes, int n_in,
                              void* d_out, int out_size) {
    const float* hP   = (const float*)d_in[0];  // [NUM_P, DIM]
    const float* h    = (const float*)d_in[1];  // [NUM_P]
    const float* volP = (const float*)d_in[2];  // [BATN, DIM]
    float* out = (float*)d_out;                 // [val(8192) | ind(8192) | g(16384)]

    const size_t smem = (size_t)(TN * DIM + TP * DIM + TP) * sizeof(float); // 77312 B
    cudaFuncSetAttribute(k1_main, cudaFuncAttributeMaxDynamicSharedMemorySize, (int)smem);

    k0_init<<<(NUM_P + 255) / 256, 256>>>(out + 2 * BATN);
    k1_main<<<NTILES * PS, THREADS, smem>>>(hP, h, volP);
    k2_final<<<(BATN + 255) / 256, 256>>>(out);
}

// round 9
// speedup vs baseline: 1.0676x; 1.0676x over previous
#include <cuda_runtime.h>
#include <cstdint>

// Fixed problem shapes
#define NUM_P  16384
#define DIM    100
#define BATN   8192

#define TN      128                 // n per block
#define TP      128                 // p per chunk
#define THREADS 256
#define PS      16                  // P-axis splits
#define NTILES  (BATN / TN)         // 64
#define NCHUNK  (NUM_P / TP / PS)   // 8 chunks per block

// Scratch: packed (ordered_value << 32 | ~argmax_index) per sample
__device__ unsigned long long g_packed[BATN];

__device__ __forceinline__ unsigned f2ord(float f) {
    unsigned u = __float_as_uint(f);
    return (u & 0x80000000u) ? ~u : (u | 0x80000000u);
}
__device__ __forceinline__ float ord2f(unsigned u) {
    u = (u & 0x80000000u) ? (u & 0x7FFFFFFFu) : ~u;
    return __uint_as_float(u);
}
// Packed dual-FP32 FMA (sm_100+): d.lo += a.lo*b.lo ; d.hi += a.hi*b.hi
__device__ __forceinline__ void fma2(unsigned long long& d,
                                     unsigned long long a,
                                     unsigned long long b) {
    asm("fma.rn.f32x2 %0, %1, %2, %0;" : "+l"(d) : "l"(a), "l"(b));
}

__device__ __forceinline__ void cp16(unsigned s, const void* g) {
    asm volatile("cp.async.cg.shared.global [%0], [%1], 16;" :: "r"(s), "l"(g));
}
__device__ __forceinline__ void cp_commit() {
    asm volatile("cp.async.commit_group;");
}
__device__ __forceinline__ void cp_wait0() {
    asm volatile("cp.async.wait_group 0;" ::: "memory");
}

__global__ void k0_init(float* __restrict__ out_g) {
    int i = blockIdx.x * blockDim.x + threadIdx.x;
    if (i < NUM_P) out_g[i] = 0.0f;
    if (i < BATN)  g_packed[i] = 0ull;
}

extern __shared__ float smem_dyn[];

// smem layout (floats): svol[12800] | shp0[12800] | shp1[12800] | h0[128] | h1[128]
#define SV_OFF  0
#define HP_OFF  (TN * DIM)
#define HH_OFF  (TN * DIM + 2 * TP * DIM)
#define SMEM_FLOATS (TN * DIM + 2 * TP * DIM + 2 * TP)

__global__ __launch_bounds__(THREADS, 1) void k1_main(
    const float* __restrict__ hP,
    const float* __restrict__ h,
    const float* __restrict__ volP)
{
    float* svol = smem_dyn + SV_OFF;

    const int tid  = threadIdx.x;
    const int lane = tid & 31;
    const int warp = tid >> 5;
    const int pl  = lane & 3;    // 4 p-lane-groups (adjacent rows -> conflict-free)
    const int nl  = lane >> 2;   // 8 n-lane-groups
    const int wpi = warp & 3;    // 4 p-warps
    const int wni = warp >> 2;   // 2 n-warps

    const int nb = blockIdx.x & (NTILES - 1);
    const int pb = blockIdx.x >> 6;

    const unsigned smem_base = (unsigned)__cvta_generic_to_shared(smem_dyn);

    // Async load of this block's volP tile (resident for whole kernel)
    {
        const float4* gv = (const float4*)(volP + (size_t)nb * TN * DIM);
        #pragma unroll 4
        for (int i = tid; i < TN * DIM / 4; i += THREADS)
            cp16(smem_base + SV_OFF * 4 + i * 16, gv + i);
    }

    // Prefetch chunk 0 into buffer 0
    {
        const int p0 = (pb * NCHUNK + 0) * TP;
        const float4* gp = (const float4*)(hP + (size_t)p0 * DIM);
        #pragma unroll 4
        for (int i = tid; i < TP * DIM / 4; i += THREADS)
            cp16(smem_base + HP_OFF * 4 + i * 16, gp + i);
        if (tid < TP / 4)
            cp16(smem_base + HH_OFF * 4 + tid * 16, ((const float4*)(h + p0)) + tid);
    }
    cp_commit();
    cp_wait0();
    __syncthreads();

    // Per-thread row/col bases
    const int prow0 = pl + 4 * wpi;     // + 16*i  (i = 0..7)
    const int ncol0 = nl + 8 * wni;     // + 16*j  (j = 0..7)

    // Hoisted B-row base pointers (keeps address IMADs out of the d-loop)
    const float* bptr[8];
    #pragma unroll
    for (int j = 0; j < 8; j++) bptr[j] = &svol[(ncol0 + 16 * j) * DIM];

    float vmax[8];
    int   vidx[8];
    #pragma unroll
    for (int j = 0; j < 8; j++) { vmax[j] = -3.4e38f; vidx[j] = 0; }

    for (int c = 0; c < NCHUNK; c++) {
        const int   buf = c & 1;
        const int   p0  = (pb * NCHUNK + c) * TP;
        const float* A  = smem_dyn + HP_OFF + buf * TP * DIM;
        const float* HH = smem_dyn + HH_OFF + buf * TP;

        // Prefetch next chunk into the other buffer (safe: prev users synced)
        if (c + 1 < NCHUNK) {
            const int nbuf = buf ^ 1;
            const int p1 = (pb * NCHUNK + c + 1) * TP;
            const float4* gp = (const float4*)(hP + (size_t)p1 * DIM);
            #pragma unroll 4
            for (int i = tid; i < TP * DIM / 4; i += THREADS)
                cp16(smem_base + (HP_OFF + nbuf * TP * DIM) * 4 + i * 16, gp + i);
            if (tid < TP / 4)
                cp16(smem_base + (HH_OFF + nbuf * TP) * 4 + tid * 16,
                     ((const float4*)(h + p1)) + tid);
            cp_commit();
        }

        // Hoisted A-row base pointers for this chunk
        const float* aptr[8];
        #pragma unroll
        for (int i = 0; i < 8; i++) aptr[i] = &A[(prow0 + 16 * i) * DIM];

        // ---- 8p x 8n register-tile GEMM over DIM ----
        unsigned long long acc[8][8];
        #pragma unroll
        for (int i = 0; i < 8; i++)
            #pragma unroll
            for (int j = 0; j < 8; j++) acc[i][j] = 0ull;

        #pragma unroll 1
        for (int d = 0; d < DIM; d += 4) {
            ulonglong2 b[8];
            #pragma unroll
            for (int j = 0; j < 8; j++)
                b[j] = *(const ulonglong2*)(bptr[j] + d);
            #pragma unroll
            for (int i = 0; i < 8; i++) {
                ulonglong2 a = *(const ulonglong2*)(aptr[i] + d);
                #pragma unroll
                for (int j = 0; j < 8; j++) {
                    fma2(acc[i][j], a.x, b[j].x);
                    fma2(acc[i][j], a.y, b[j].y);
                }
            }
        }

        // ---- epilogue: fold pair, add h, merge running (max, argmax) ----
        #pragma unroll
        for (int i = 0; i < 8; i++) {
            const int   pr = prow0 + 16 * i;
            const float hv = HH[pr];
            const int   p  = p0 + pr;
            #pragma unroll
            for (int j = 0; j < 8; j++) {
                float lo = __uint_as_float((unsigned)(acc[i][j]));
                float hi = __uint_as_float((unsigned)(acc[i][j] >> 32));
                float s  = lo + hi + hv;
                if (s > vmax[j]) { vmax[j] = s; vidx[j] = p; }  // '>' keeps earliest p
            }
        }

        if (c + 1 < NCHUNK) cp_wait0();
        __syncthreads();
    }

    // ---- intra-warp merge across the 4 p-lane-groups (xor 1, 2), then global ----
    #pragma unroll
    for (int j = 0; j < 8; j++) {
        unsigned long long pk = ((unsigned long long)f2ord(vmax[j]) << 32)
                              | (unsigned long long)(~(unsigned)vidx[j]);
        #pragma unroll
        for (int m = 1; m <= 2; m <<= 1) {
            unsigned long long o = __shfl_xor_sync(0xffffffffu, pk, m);
            if (o > pk) pk = o;
        }
        if (pl == 0) {
            const int n = nb * TN + ncol0 + 16 * j;
            atomicMax(&g_packed[n], pk);
        }
    }
}

__global__ void k2_final(float* __restrict__ out) {
    int n = blockIdx.x * blockDim.x + threadIdx.x;
    if (n >= BATN) return;
    unsigned long long pk = g_packed[n];
    unsigned ub = (unsigned)(pk >> 32);
    unsigned p  = ~(unsigned)pk;
    out[n]        = ord2f(ub);           // tot_ind_val
    out[BATN + n] = (float)p;            // tot_ind (as float)
    atomicAdd(&out[2 * BATN + p], 1.0f / (float)BATN);  // g (exact pow2 summands)
}

extern "C" void kernel_launch(void* const* d_in, const int* in_sizes, int n_in,
                              void* d_out, int out_size) {
    const float* hP   = (const float*)d_in[0];  // [NUM_P, DIM]
    const float* h    = (const float*)d_in[1];  // [NUM_P]
    const float* volP = (const float*)d_in[2];  // [BATN, DIM]
    float* out = (float*)d_out;                 // [val(8192) | ind(8192) | g(16384)]

    const size_t smem = (size_t)SMEM_FLOATS * sizeof(float);  // 154,624 B
    cudaFuncSetAttribute(k1_main, cudaFuncAttributeMaxDynamicSharedMemorySize, (int)smem);

    k0_init<<<(NUM_P + 255) / 256, 256>>>(out + 2 * BATN);
    k1_main<<<NTILES * PS, THREADS, smem>>>(hP, h, volP);
    k2_final<<<(BATN + 255) / 256, 256>>>(out);
}

// round 12
// speedup vs baseline: 2.2047x; 2.0651x over previous
#include <cuda_runtime.h>
#include <cuda_bf16.h>
#include <cstdint>

// ---------------- fixed shapes ----------------
#define NUM_P  16384
#define DIM    100
#define BATN   8192
#define KD     112                  // 7 x k16, cols 100..111 zero

// ---------------- device scratch ----------------
__device__ unsigned long long g_packed[BATN];
__device__ unsigned amax_ord[BATN];
__device__ __align__(16) __nv_bfloat16 A_img[BATN * KD];    // volP rows, bf16
__device__ __align__(16) __nv_bfloat16 B_img[NUM_P * KD];   // hP rows, bf16
__device__ __align__(16) __nv_bfloat16 scores[(size_t)BATN * NUM_P]; // [n][p]

// ---------------- helpers ----------------
__device__ __forceinline__ unsigned f2ord(float f) {
    unsigned u = __float_as_uint(f);
    return (u & 0x80000000u) ? ~u : (u | 0x80000000u);
}
__device__ __forceinline__ float ord2f(unsigned u) {
    u = (u & 0x80000000u) ? (u & 0x7FFFFFFFu) : ~u;
    return __uint_as_float(u);
}
__device__ __forceinline__ void cp16(uint32_t s, const void* g) {
    asm volatile("cp.async.cg.shared.global [%0], [%1], 16;" :: "r"(s), "l"(g));
}
__device__ __forceinline__ void cp_commit() { asm volatile("cp.async.commit_group;"); }
__device__ __forceinline__ void cp_wait0()  { asm volatile("cp.async.wait_group 0;" ::: "memory"); }

__device__ __forceinline__ void ldsm4(uint32_t* r, uint32_t addr) {
    asm volatile("ldmatrix.sync.aligned.m8n8.x4.shared.b16 {%0,%1,%2,%3}, [%4];"
                 : "=r"(r[0]), "=r"(r[1]), "=r"(r[2]), "=r"(r[3]) : "r"(addr));
}
__device__ __forceinline__ void mma16816(float* c, const uint32_t* a, const uint32_t* b) {
    asm volatile("mma.sync.aligned.m16n8k16.row.col.f32.bf16.bf16.f32 "
                 "{%0,%1,%2,%3}, {%4,%5,%6,%7}, {%8,%9}, {%0,%1,%2,%3};"
                 : "+f"(c[0]), "+f"(c[1]), "+f"(c[2]), "+f"(c[3])
                 : "r"(a[0]), "r"(a[1]), "r"(a[2]), "r"(a[3]), "r"(b[0]), "r"(b[1]));
}
__device__ __forceinline__ void sts32(uint32_t addr, uint32_t v) {
    asm volatile("st.shared.b32 [%0], %1;" :: "r"(addr), "r"(v));
}
__device__ __forceinline__ float2 lds64f(uint32_t addr) {
    float2 r;
    asm volatile("ld.shared.v2.f32 {%0,%1}, [%2];" : "=f"(r.x), "=f"(r.y) : "r"(addr));
    return r;
}

// ---------------- k0: init ----------------
__global__ void k0_init(float* __restrict__ out_g) {
    int i = blockIdx.x * blockDim.x + threadIdx.x;
    if (i < NUM_P) out_g[i] = 0.0f;
    if (i < BATN)  { g_packed[i] = 0ull; amax_ord[i] = 0u; }
}

// ---------------- k_prep: bf16 images (K padded to 112) ----------------
#define AGRP (BATN * (KD/8))     // 114688
#define BGRP (NUM_P * (KD/8))    // 229376
__global__ void k_prep(const float* __restrict__ hP,
                       const float* __restrict__ volP) {
    int g = blockIdx.x * blockDim.x + threadIdx.x;
    if (g >= AGRP + BGRP) return;
    union { __nv_bfloat16 b[8]; uint4 v; } u;
    if (g < AGRP) {
        int n = g / (KD/8), c0 = (g - n * (KD/8)) * 8;
        const float* src = volP + (size_t)n * DIM;
        #pragma unroll
        for (int j = 0; j < 8; j++) {
            int c = c0 + j;
            u.b[j] = (c < DIM) ? __float2bfloat16(src[c]) : __float2bfloat16(0.0f);
        }
        *(uint4*)&A_img[(size_t)n * KD + c0] = u.v;
    } else {
        int b = g - AGRP;
        int p = b / (KD/8), c0 = (b - p * (KD/8)) * 8;
        const float* src = hP + (size_t)p * DIM;
        #pragma unroll
        for (int j = 0; j < 8; j++) {
            int c = c0 + j;
            u.b[j] = (c < DIM) ? __float2bfloat16(src[c]) : __float2bfloat16(0.0f);
        }
        *(uint4*)&B_img[(size_t)p * KD + c0] = u.v;
    }
}

// ---------------- k_gemm: bf16 mma.sync, approx scores + per-n max ----------------
// smem bytes: A[128x240] | B0[128x240] | B1 | h0[512] | h1[512] | OUT[128x272]
#define SAROW 240
#define SA    0
#define SB0   30720
#define SB1   61440
#define SH0   92160
#define SH1   92672
#define SOUT  93184
#define OROW  272
#define SMTOT (SOUT + 128 * OROW)   // 128000

#define NCH   (NUM_P / 2 / 128)     // 64 chunks per CTA (PSPLIT=2)

extern __shared__ unsigned char smg[];

__global__ __launch_bounds__(256, 1) void k_gemm(const float* __restrict__ h) {
    const int tid  = threadIdx.x;
    const int lane = tid & 31;
    const int wid  = tid >> 5;
    const int wn   = wid & 3;    // n quadrant (32 rows)
    const int wp   = wid >> 2;   // p half (64 cols)
    const uint32_t sb = (uint32_t)__cvta_generic_to_shared(smg);

    const int nb = blockIdx.x & 63;
    const int pb = blockIdx.x >> 6;
    const int nrow0 = nb * 128;
    const int pcol0 = pb * (NUM_P / 2);

    // ---- prologue: A tile + B chunk0 + h chunk0 ----
    {
        #pragma unroll 4
        for (int i = tid; i < 128 * (KD/8); i += 256) {
            int r = i / (KD/8), q = i % (KD/8);
            cp16(sb + SA + r * SAROW + q * 16, &A_img[(size_t)(nrow0 + r) * KD + q * 8]);
            cp16(sb + SB0 + r * SAROW + q * 16, &B_img[(size_t)(pcol0 + r) * KD + q * 8]);
        }
        if (tid < 32) cp16(sb + SH0 + tid * 16, h + pcol0 + tid * 4);
    }
    cp_commit(); cp_wait0();
    __syncthreads();

    // ---- persistent A fragments: 2 mi x 7 k16 x 4 regs ----
    uint32_t aF[2][7][4];
    {
        const uint32_t abase = sb + SA + (uint32_t)(wn * 32 + (lane & 15)) * SAROW + ((lane >> 4) * 16);
        #pragma unroll
        for (int mi = 0; mi < 2; mi++)
            #pragma unroll
            for (int k = 0; k < 7; k++)
                ldsm4(aF[mi][k], abase + mi * 16 * SAROW + k * 32);
    }

    // B ldmatrix per-lane offsets (4 pig groups of 16 p-rows)
    uint32_t bOff[4];
    #pragma unroll
    for (int pig = 0; pig < 4; pig++) {
        int prow = wp * 64 + pig * 16 + (lane & 7) + ((lane >> 4) & 1) * 8;
        bOff[pig] = (uint32_t)prow * SAROW + ((lane >> 3) & 1) * 16;
    }

    float vmax[4] = {-3.4e38f, -3.4e38f, -3.4e38f, -3.4e38f};

    for (int c = 0; c < NCH; c++) {
        const int buf = c & 1;

        // prefetch next B + h into buf^1 (its chunk-(c-1) readers passed last barrier)
        if (c + 1 < NCH) {
            const uint32_t bd = sb + ((buf ^ 1) ? SB1 : SB0);
            const int p1 = pcol0 + (c + 1) * 128;
            #pragma unroll 4
            for (int i = tid; i < 128 * (KD/8); i += 256) {
                int r = i / (KD/8), q = i % (KD/8);
                cp16(bd + r * SAROW + q * 16, &B_img[(size_t)(p1 + r) * KD + q * 8]);
            }
            if (tid < 32) cp16(sb + ((buf ^ 1) ? SH1 : SH0) + tid * 16, h + p1 + tid * 4);
            cp_commit();
        }

        // ---- mma mainloop: 32n x 128p per warp (2mi x 8pi x 7k) ----
        float acc[2][8][4];
        #pragma unroll
        for (int mi = 0; mi < 2; mi++)
            #pragma unroll
            for (int pi = 0; pi < 8; pi++)
                #pragma unroll
                for (int q = 0; q < 4; q++) acc[mi][pi][q] = 0.0f;

        const uint32_t bb = sb + (buf ? SB1 : SB0);
        #pragma unroll
        for (int k = 0; k < 7; k++) {
            uint32_t bf[4][4];
            #pragma unroll
            for (int pig = 0; pig < 4; pig++) ldsm4(bf[pig], bb + bOff[pig] + k * 32);
            #pragma unroll
            for (int mi = 0; mi < 2; mi++)
                #pragma unroll
                for (int pi = 0; pi < 8; pi++)
                    mma16816(acc[mi][pi], aF[mi][k], &bf[pi >> 1][(pi & 1) * 2]);
        }

        // ---- epilogue: + h, track max, stage bf16 tile ----
        const uint32_t hb = sb + (buf ? SH1 : SH0);
        const int g = lane >> 2;
        #pragma unroll
        for (int pi = 0; pi < 8; pi++) {
            const int colL = wp * 64 + pi * 8 + 2 * (lane & 3);
            float2 hv = lds64f(hb + colL * 4);
            #pragma unroll
            for (int mi = 0; mi < 2; mi++) {
                float* cc = acc[mi][pi];
                float s0 = cc[0] + hv.x, s1 = cc[1] + hv.y;
                float s2 = cc[2] + hv.x, s3 = cc[3] + hv.y;
                vmax[mi * 2 + 0] = fmaxf(vmax[mi * 2 + 0], fmaxf(s0, s1));
                vmax[mi * 2 + 1] = fmaxf(vmax[mi * 2 + 1], fmaxf(s2, s3));
                __nv_bfloat162 p0 = __floats2bfloat162_rn(s0, s1);
                __nv_bfloat162 p1 = __floats2bfloat162_rn(s2, s3);
                const uint32_t row = (uint32_t)(wn * 32 + mi * 16 + g);
                sts32(sb + SOUT + row * OROW + colL * 2, *(uint32_t*)&p0);
                sts32(sb + SOUT + (row + 8) * OROW + colL * 2, *(uint32_t*)&p1);
            }
        }

        cp_wait0();
        __syncthreads();

        // ---- cooperative STG of the staged 128x128 bf16 tile ----
        {
            const size_t pc = (size_t)pcol0 + (size_t)c * 128;
            #pragma unroll
            for (int i = tid; i < 2048; i += 256) {
                int r = i >> 4, q = i & 15;
                uint4 v = *(uint4*)(smg + SOUT + r * OROW + q * 16);
                *(uint4*)&scores[((size_t)(nrow0 + r)) * NUM_P + pc + q * 8] = v;
            }
        }
        __syncthreads();
    }

    // ---- publish per-n approximate max ----
    #pragma unroll
    for (int s = 0; s < 4; s++) {
        float v = vmax[s];
        v = fmaxf(v, __shfl_xor_sync(0xffffffffu, v, 1));
        v = fmaxf(v, __shfl_xor_sync(0xffffffffu, v, 2));
        if ((lane & 3) == 0) {
            int n = nrow0 + wn * 32 + (s >> 1) * 16 + (s & 1) * 8 + (lane >> 2);
            atomicMax(&amax_ord[n], f2ord(v));
        }
    }
}

// ---------------- k_scan: threshold + exact fp32 rescore ----------------
#define MARGIN 0.35f
__global__ __launch_bounds__(256) void k_scan(const float* __restrict__ hP,
                                              const float* __restrict__ h,
                                              const float* __restrict__ volP) {
    const int n   = blockIdx.x >> 3;
    const int seg = blockIdx.x & 7;
    const int p0  = seg * 2048 + threadIdx.x * 8;

    const float th = ord2f(amax_ord[n]) - MARGIN;
    union { uint4 v; __nv_bfloat16 b[8]; } u;
    u.v = *(const uint4*)&scores[(size_t)n * NUM_P + p0];

    const float4* va = (const float4*)(volP + (size_t)n * DIM);

    #pragma unroll
    for (int j = 0; j < 8; j++) {
        if (__bfloat162float(u.b[j]) >= th) {
            const int p = p0 + j;
            const float4* vb = (const float4*)(hP + (size_t)p * DIM);
            float acc = h[p];
            #pragma unroll 5
            for (int i = 0; i < DIM / 4; i++) {
                float4 x = va[i], y = vb[i];
                acc = fmaf(x.x, y.x, acc);
                acc = fmaf(x.y, y.y, acc);
                acc = fmaf(x.z, y.z, acc);
                acc = fmaf(x.w, y.w, acc);
            }
            unsigned long long pk = ((unsigned long long)f2ord(acc) << 32)
                                  | (unsigned long long)(~(unsigned)p);
            atomicMax(&g_packed[n], pk);
        }
    }
}

// ---------------- k2: finalize ----------------
__global__ void k2_final(float* __restrict__ out) {
    int n = blockIdx.x * blockDim.x + threadIdx.x;
    if (n >= BATN) return;
    unsigned long long pk = g_packed[n];
    unsigned ub = (unsigned)(pk >> 32);
    unsigned p  = ~(unsigned)pk;
    out[n]        = ord2f(ub);           // tot_ind_val
    out[BATN + n] = (float)p;            // tot_ind (as float)
    atomicAdd(&out[2 * BATN + p], 1.0f / (float)BATN);  // g (exact pow2 summands)
}

extern "C" void kernel_launch(void* const* d_in, const int* in_sizes, int n_in,
                              void* d_out, int out_size) {
    const float* hP   = (const float*)d_in[0];  // [NUM_P, DIM]
    const float* h    = (const float*)d_in[1];  // [NUM_P]
    const float* volP = (const float*)d_in[2];  // [BATN, DIM]
    float* out = (float*)d_out;                 // [val(8192) | ind(8192) | g(16384)]

    cudaFuncSetAttribute(k_gemm, cudaFuncAttributeMaxDynamicSharedMemorySize, SMTOT);

    k0_init<<<(NUM_P + 255) / 256, 256>>>(out + 2 * BATN);
    k_prep<<<(AGRP + BGRP + 255) / 256, 256>>>(hP, volP);
    k_gemm<<<128, 256, SMTOT>>>(h);
    k_scan<<<BATN * 8, 256>>>(hP, h, volP);
    k2_final<<<(BATN + 255) / 256, 256>>>(out);
}

// round 15
// speedup vs baseline: 2.8394x; 1.2879x over previous
#include <cuda_runtime.h>
#include <cuda_bf16.h>
#include <cstdint>

// ---------------- fixed shapes ----------------
#define NUM_P  16384
#define DIM    100
#define BATN   8192
#define KD     112                  // 7 x k16, cols 100..111 zero
#define NBLK   (NUM_P / 64)         // 256 64-p blocks
#define MARGIN 0.25f

// ---------------- device scratch ----------------
__device__ unsigned long long g_packed[BATN];
__device__ __align__(16) float blkmax[(size_t)BATN * NBLK];   // per (n, 64p-block) approx max
__device__ __align__(16) __nv_bfloat16 A_img[BATN * KD];      // volP rows, bf16
__device__ __align__(16) __nv_bfloat16 B_img[NUM_P * KD];     // hP rows, bf16

// ---------------- helpers ----------------
__device__ __forceinline__ unsigned f2ord(float f) {
    unsigned u = __float_as_uint(f);
    return (u & 0x80000000u) ? ~u : (u | 0x80000000u);
}
__device__ __forceinline__ float ord2f(unsigned u) {
    u = (u & 0x80000000u) ? (u & 0x7FFFFFFFu) : ~u;
    return __uint_as_float(u);
}
__device__ __forceinline__ void cp16(uint32_t s, const void* g) {
    asm volatile("cp.async.cg.shared.global [%0], [%1], 16;" :: "r"(s), "l"(g));
}
__device__ __forceinline__ void cp_commit() { asm volatile("cp.async.commit_group;"); }
__device__ __forceinline__ void cp_wait0()  { asm volatile("cp.async.wait_group 0;" ::: "memory"); }

__device__ __forceinline__ void ldsm4(uint32_t* r, uint32_t addr) {
    asm volatile("ldmatrix.sync.aligned.m8n8.x4.shared.b16 {%0,%1,%2,%3}, [%4];"
                 : "=r"(r[0]), "=r"(r[1]), "=r"(r[2]), "=r"(r[3]) : "r"(addr));
}
__device__ __forceinline__ void mma16816(float* c, const uint32_t* a, const uint32_t* b) {
    asm volatile("mma.sync.aligned.m16n8k16.row.col.f32.bf16.bf16.f32 "
                 "{%0,%1,%2,%3}, {%4,%5,%6,%7}, {%8,%9}, {%0,%1,%2,%3};"
                 : "+f"(c[0]), "+f"(c[1]), "+f"(c[2]), "+f"(c[3])
                 : "r"(a[0]), "r"(a[1]), "r"(a[2]), "r"(a[3]), "r"(b[0]), "r"(b[1]));
}
__device__ __forceinline__ float2 lds64f(uint32_t addr) {
    float2 r;
    asm volatile("ld.shared.v2.f32 {%0,%1}, [%2];" : "=f"(r.x), "=f"(r.y) : "r"(addr));
    return r;
}

// ---------------- k0: init ----------------
__global__ void k0_init(float* __restrict__ out_g) {
    int i = blockIdx.x * blockDim.x + threadIdx.x;
    if (i < NUM_P) out_g[i] = 0.0f;
    if (i < BATN)  g_packed[i] = 0ull;
}

// ---------------- k_prep: bf16 images (K padded to 112) ----------------
#define AGRP (BATN * (KD/8))     // 114688
#define BGRP (NUM_P * (KD/8))    // 229376
__global__ void k_prep(const float* __restrict__ hP,
                       const float* __restrict__ volP) {
    int g = blockIdx.x * blockDim.x + threadIdx.x;
    if (g >= AGRP + BGRP) return;
    union { __nv_bfloat16 b[8]; uint4 v; } u;
    if (g < AGRP) {
        int n = g / (KD/8), c0 = (g - n * (KD/8)) * 8;
        const float* src = volP + (size_t)n * DIM;
        #pragma unroll
        for (int j = 0; j < 8; j++) {
            int c = c0 + j;
            u.b[j] = (c < DIM) ? __float2bfloat16(src[c]) : __float2bfloat16(0.0f);
        }
        *(uint4*)&A_img[(size_t)n * KD + c0] = u.v;
    } else {
        int b = g - AGRP;
        int p = b / (KD/8), c0 = (b - p * (KD/8)) * 8;
        const float* src = hP + (size_t)p * DIM;
        #pragma unroll
        for (int j = 0; j < 8; j++) {
            int c = c0 + j;
            u.b[j] = (c < DIM) ? __float2bfloat16(src[c]) : __float2bfloat16(0.0f);
        }
        *(uint4*)&B_img[(size_t)p * KD + c0] = u.v;
    }
}

// ---------------- k_gemm: bf16 mma.sync -> per-(n,64p-block) max ----------------
// smem bytes: A[128x240] | B0[128x240] | B1 | h0[512] | h1[512]
#define SAROW 240
#define SA    0
#define SB0   30720
#define SB1   61440
#define SH0   92160
#define SH1   92672
#define SMTOT 93184

#define NCH   (NUM_P / 2 / 128)     // 64 chunks per CTA (PSPLIT=2)

extern __shared__ unsigned char smg[];

__global__ __launch_bounds__(256, 1) void k_gemm(const float* __restrict__ h) {
    const int tid  = threadIdx.x;
    const int lane = tid & 31;
    const int wid  = tid >> 5;
    const int wn   = wid & 3;    // n quadrant (32 rows)
    const int wp   = wid >> 2;   // p half (64 cols)
    const uint32_t sb = (uint32_t)__cvta_generic_to_shared(smg);

    const int nb = blockIdx.x & 63;
    const int pb = blockIdx.x >> 6;
    const int nrow0 = nb * 128;
    const int pcol0 = pb * (NUM_P / 2);

    // ---- prologue: A tile + B chunk0 + h chunk0 ----
    {
        #pragma unroll 4
        for (int i = tid; i < 128 * (KD/8); i += 256) {
            int r = i / (KD/8), q = i % (KD/8);
            cp16(sb + SA + r * SAROW + q * 16, &A_img[(size_t)(nrow0 + r) * KD + q * 8]);
            cp16(sb + SB0 + r * SAROW + q * 16, &B_img[(size_t)(pcol0 + r) * KD + q * 8]);
        }
        if (tid < 32) cp16(sb + SH0 + tid * 16, h + pcol0 + tid * 4);
    }
    cp_commit(); cp_wait0();
    __syncthreads();

    // ---- persistent A fragments: 2 mi x 7 k16 x 4 regs ----
    uint32_t aF[2][7][4];
    {
        const uint32_t abase = sb + SA + (uint32_t)(wn * 32 + (lane & 15)) * SAROW + ((lane >> 4) * 16);
        #pragma unroll
        for (int mi = 0; mi < 2; mi++)
            #pragma unroll
            for (int k = 0; k < 7; k++)
                ldsm4(aF[mi][k], abase + mi * 16 * SAROW + k * 32);
    }

    // B ldmatrix per-lane offsets (4 pig groups of 16 p-rows)
    uint32_t bOff[4];
    #pragma unroll
    for (int pig = 0; pig < 4; pig++) {
        int prow = wp * 64 + pig * 16 + (lane & 7) + ((lane >> 4) & 1) * 8;
        bOff[pig] = (uint32_t)prow * SAROW + ((lane >> 3) & 1) * 16;
    }

    for (int c = 0; c < NCH; c++) {
        const int buf = c & 1;

        // prefetch next B + h into buf^1 (chunk c-1 readers passed last barrier)
        if (c + 1 < NCH) {
            const uint32_t bd = sb + ((buf ^ 1) ? SB1 : SB0);
            const int p1 = pcol0 + (c + 1) * 128;
            #pragma unroll 4
            for (int i = tid; i < 128 * (KD/8); i += 256) {
                int r = i / (KD/8), q = i % (KD/8);
                cp16(bd + r * SAROW + q * 16, &B_img[(size_t)(p1 + r) * KD + q * 8]);
            }
            if (tid < 32) cp16(sb + ((buf ^ 1) ? SH1 : SH0) + tid * 16, h + p1 + tid * 4);
            cp_commit();
        }

        // ---- mma mainloop: 32n x 128p per warp (2mi x 8pi x 7k) ----
        float acc[2][8][4];
        #pragma unroll
        for (int mi = 0; mi < 2; mi++)
            #pragma unroll
            for (int pi = 0; pi < 8; pi++)
                #pragma unroll
                for (int q = 0; q < 4; q++) acc[mi][pi][q] = 0.0f;

        const uint32_t bb = sb + (buf ? SB1 : SB0);
        #pragma unroll
        for (int k = 0; k < 7; k++) {
            uint32_t bf[4][4];
            #pragma unroll
            for (int pig = 0; pig < 4; pig++) ldsm4(bf[pig], bb + bOff[pig] + k * 32);
            #pragma unroll
            for (int mi = 0; mi < 2; mi++)
                #pragma unroll
                for (int pi = 0; pi < 8; pi++)
                    mma16816(acc[mi][pi], aF[mi][k], &bf[pi >> 1][(pi & 1) * 2]);
        }

        // ---- epilogue: + h, per-row 64-col max, direct STG of block max ----
        const uint32_t hb = sb + (buf ? SH1 : SH0);
        float vloc[4] = {-3.4e38f, -3.4e38f, -3.4e38f, -3.4e38f};
        #pragma unroll
        for (int pi = 0; pi < 8; pi++) {
            const int colL = wp * 64 + pi * 8 + 2 * (lane & 3);
            float2 hv = lds64f(hb + colL * 4);
            #pragma unroll
            for (int mi = 0; mi < 2; mi++) {
                float* cc = acc[mi][pi];
                vloc[mi * 2 + 0] = fmaxf(vloc[mi * 2 + 0], fmaxf(cc[0] + hv.x, cc[1] + hv.y));
                vloc[mi * 2 + 1] = fmaxf(vloc[mi * 2 + 1], fmaxf(cc[2] + hv.x, cc[3] + hv.y));
            }
        }
        const int blk = pb * 128 + c * 2 + wp;   // global 64-p block index
        #pragma unroll
        for (int s = 0; s < 4; s++) {
            float v = vloc[s];
            v = fmaxf(v, __shfl_xor_sync(0xffffffffu, v, 1));
            v = fmaxf(v, __shfl_xor_sync(0xffffffffu, v, 2));
            if ((lane & 3) == 0) {
                int n = nrow0 + wn * 32 + (s >> 1) * 16 + (s & 1) * 8 + (lane >> 2);
                blkmax[(size_t)n * NBLK + blk] = v;   // unique producer -> plain STG
            }
        }

        if (c + 1 < NCH) cp_wait0();
        __syncthreads();
    }
}

// ---------------- k_scan2: threshold block maxima + exact fp32 rescore ----------------
__global__ __launch_bounds__(128) void k_scan2(const float* __restrict__ hP,
                                               const float* __restrict__ h,
                                               const float* __restrict__ volP) {
    const int n   = blockIdx.x;
    const int tid = threadIdx.x;
    __shared__ float sm_bm[NBLK];
    __shared__ float sm_va[DIM];
    __shared__ float sm_red[4];
    __shared__ int   sm_cand[NBLK];
    __shared__ int   sm_cc;

    // stage block maxima + this n's volP row
    #pragma unroll
    for (int i = tid; i < NBLK; i += 128) sm_bm[i] = blkmax[(size_t)n * NBLK + i];
    if (tid < DIM) sm_va[tid] = volP[(size_t)n * DIM + tid];
    if (tid == 0) sm_cc = 0;
    __syncthreads();

    // global max over 256 block maxima
    float m = fmaxf(sm_bm[tid], sm_bm[tid + 128]);
    #pragma unroll
    for (int o = 16; o; o >>= 1) m = fmaxf(m, __shfl_xor_sync(0xffffffffu, m, o));
    if ((tid & 31) == 0) sm_red[tid >> 5] = m;
    __syncthreads();
    const float th = fmaxf(fmaxf(sm_red[0], sm_red[1]), fmaxf(sm_red[2], sm_red[3])) - MARGIN;

    // gather candidate blocks
    for (int i = tid; i < NBLK; i += 128)
        if (sm_bm[i] >= th) sm_cand[atomicAdd(&sm_cc, 1)] = i;
    __syncthreads();

    // hardening: guarantee >=1 candidate so every g_packed[n] is written
    // (cc==0 should be impossible; this removes the UB path if it ever happens)
    int cc = sm_cc;
    if (cc == 0) { if (tid == 0) sm_cand[0] = 0; cc = 1; }
    __syncthreads();

    // exact fp32 rescore: 2 candidate blocks per pass (128 threads, 1 p each)
    for (int ci = 0; ci < cc; ci += 2) {
        const int which = ci + (tid >> 6);
        if (which < cc) {
            const int p = sm_cand[which] * 64 + (tid & 63);
            const float4* vb = (const float4*)(hP + (size_t)p * DIM);
            float acc = h[p];
            #pragma unroll 5
            for (int i = 0; i < DIM / 4; i++) {
                float4 y = __ldg(vb + i);
                acc = fmaf(sm_va[4*i+0], y.x, acc);
                acc = fmaf(sm_va[4*i+1], y.y, acc);
                acc = fmaf(sm_va[4*i+2], y.z, acc);
                acc = fmaf(sm_va[4*i+3], y.w, acc);
            }
            unsigned long long pk = ((unsigned long long)f2ord(acc) << 32)
                                  | (unsigned long long)(~(unsigned)p);
            atomicMax(&g_packed[n], pk);
        }
    }
}

// ---------------- k2: finalize ----------------
__global__ void k2_final(float* __restrict__ out) {
    int n = blockIdx.x * blockDim.x + threadIdx.x;
    if (n >= BATN) return;
    unsigned long long pk = g_packed[n];
    unsigned ub = (unsigned)(pk >> 32);
    unsigned p  = (~(unsigned)pk) & (NUM_P - 1);   // mask = identity for valid p; kills wild-write UB
    out[n]        = ord2f(ub);           // tot_ind_val
    out[BATN + n] = (float)p;            // tot_ind (as float)
    atomicAdd(&out[2 * BATN + p], 1.0f / (float)BATN);  // g (exact pow2 summands)
}

extern "C" void kernel_launch(void* const* d_in, const int* in_sizes, int n_in,
                              void* d_out, int out_size) {
    const float* hP   = (const float*)d_in[0];  // [NUM_P, DIM]
    const float* h    = (const float*)d_in[1];  // [NUM_P]
    const float* volP = (const float*)d_in[2];  // [BATN, DIM]
    float* out = (float*)d_out;                 // [val(8192) | ind(8192) | g(16384)]

    cudaFuncSetAttribute(k_gemm, cudaFuncAttributeMaxDynamicSharedMemorySize, SMTOT);

    k0_init<<<(NUM_P + 255) / 256, 256>>>(out + 2 * BATN);
    k_prep<<<(AGRP + BGRP + 255) / 256, 256>>>(hP, volP);
    k_gemm<<<128, 256, SMTOT>>>(h);
    k_scan2<<<BATN, 128>>>(hP, h, volP);
    k2_final<<<(BATN + 255) / 256, 256>>>(out);
}